// round 2
// baseline (speedup 1.0000x reference)
#include <cuda_runtime.h>
#include <math.h>

// MatchLoss: for each src point (16384 x 3 fp32), find 2nd-nearest tgt point
// (16384 x 3), pd = ||src - tgt[idx2] + 1e-6||, mv = (pd<1e-3)+1e-7,
// out = log(1 + sum(exp(mv))).
#define NPTS          16384
#define NSPLIT        8          // warps per block, each scans 1/8 of tgt tile
#define TILE          2048       // tgt points staged in SMEM per tile
#define SRC_PER_THREAD 4
#define SRC_PER_BLOCK (32 * SRC_PER_THREAD)   // 128
#define THREADS       256

#define RADIUS_F  1e-3f
#define EPS_F     1e-7f
#define PD_EPS_F  1e-6f
#define BIG       3.402823466e+38f

__device__ float g_sum;

__global__ void ml_zero_kernel() { g_sum = 0.0f; }

__global__ __launch_bounds__(THREADS)
void ml_nn2_kernel(const float* __restrict__ src, const float* __restrict__ tgt) {
    __shared__ float4 tile[TILE];                    // 32 KB
    __shared__ float  sb1[NSPLIT][SRC_PER_BLOCK];    // 4 KB
    __shared__ float  sb2[NSPLIT][SRC_PER_BLOCK];    // 4 KB
    __shared__ int    si1[NSPLIT][SRC_PER_BLOCK];    // 4 KB
    __shared__ int    si2[NSPLIT][SRC_PER_BLOCK];    // 4 KB

    const int tid  = threadIdx.x;
    const int warp = tid >> 5;
    const int lane = tid & 31;

    // Each thread owns SRC_PER_THREAD src points: base + lane + 32*r
    const int sbase = blockIdx.x * SRC_PER_BLOCK + lane;

    float sx[SRC_PER_THREAD], sy[SRC_PER_THREAD], sz[SRC_PER_THREAD];
    float b1[SRC_PER_THREAD], b2[SRC_PER_THREAD];
    int   i1[SRC_PER_THREAD], i2[SRC_PER_THREAD];
    #pragma unroll
    for (int r = 0; r < SRC_PER_THREAD; ++r) {
        const int s = sbase + 32 * r;
        sx[r] = src[3 * s + 0];
        sy[r] = src[3 * s + 1];
        sz[r] = src[3 * s + 2];
        b1[r] = BIG; b2[r] = BIG; i1[r] = -1; i2[r] = -1;
    }

    const int chunk = TILE / NSPLIT;   // 256 tgt points per warp per tile
    const int wbase = warp * chunk;

    for (int tb = 0; tb < NPTS; tb += TILE) {
        // Cooperative tile load: tgt is L2-resident (196 KB total)
        for (int k = tid; k < TILE; k += THREADS) {
            const int p = 3 * (tb + k);
            tile[k] = make_float4(tgt[p], tgt[p + 1], tgt[p + 2], 0.0f);
        }
        __syncthreads();

        #pragma unroll 4
        for (int k = 0; k < chunk; ++k) {
            const float4 t = tile[wbase + k];        // warp-uniform -> LDS broadcast
            const int j = tb + wbase + k;

            #pragma unroll
            for (int r = 0; r < SRC_PER_THREAD; ++r) {
                const float dx = sx[r] - t.x;
                const float dy = sy[r] - t.y;
                const float dz = sz[r] - t.z;
                const float d2 = fmaf(dx, dx, fmaf(dy, dy, dz * dz));
                if (d2 < b2[r]) {                    // rarely taken
                    if (d2 < b1[r]) { b2[r] = b1[r]; i2[r] = i1[r]; b1[r] = d2; i1[r] = j; }
                    else            { b2[r] = d2;    i2[r] = j; }
                }
            }
        }
        __syncthreads();
    }

    // Publish per-split partial top-2 (value, index)
    #pragma unroll
    for (int r = 0; r < SRC_PER_THREAD; ++r) {
        sb1[warp][lane + 32 * r] = b1[r];  si1[warp][lane + 32 * r] = i1[r];
        sb2[warp][lane + 32 * r] = b2[r];  si2[warp][lane + 32 * r] = i2[r];
    }
    __syncthreads();

    // Threads 0..SRC_PER_BLOCK-1 merge the 8 partials for one src point each,
    // then compute the per-point contribution exp(match_val).
    float contrib = 0.0f;
    if (tid < SRC_PER_BLOCK) {
        float m1 = BIG, m2 = BIG;
        int   j1 = -1,  j2 = -1;
        #pragma unroll
        for (int w = 0; w < NSPLIT; ++w) {
            float d = sb1[w][tid]; int ii = si1[w][tid];
            if (d < m2) {
                if (d < m1) { m2 = m1; j2 = j1; m1 = d; j1 = ii; }
                else        { m2 = d;  j2 = ii; }
            }
            d = sb2[w][tid]; ii = si2[w][tid];
            if (d < m2) {
                if (d < m1) { m2 = m1; j2 = j1; m1 = d; j1 = ii; }
                else        { m2 = d;  j2 = ii; }
            }
        }
        const int s = blockIdx.x * SRC_PER_BLOCK + tid;
        const float px = src[3 * s + 0], py = src[3 * s + 1], pz = src[3 * s + 2];
        const float tx = tgt[3 * j2 + 0], ty = tgt[3 * j2 + 1], tz = tgt[3 * j2 + 2];
        // pd = || src - matched + PD_EPS ||  (PD_EPS added componentwise)
        const float dx = px - tx + PD_EPS_F;
        const float dy = py - ty + PD_EPS_F;
        const float dz = pz - tz + PD_EPS_F;
        const float pd = sqrtf(fmaf(dx, dx, fmaf(dy, dy, dz * dz)));
        const float mv = (pd < RADIUS_F ? 1.0f : 0.0f) + EPS_F;
        contrib = expf(mv);
    }

    // First SRC_PER_BLOCK threads hold contributions; warp-reduce + atomic.
    if (tid < SRC_PER_BLOCK) {
        #pragma unroll
        for (int o = 16; o > 0; o >>= 1)
            contrib += __shfl_down_sync(0xFFFFFFFFu, contrib, o);
        if (lane == 0) atomicAdd(&g_sum, contrib);
    }
}

__global__ void ml_final_kernel(float* __restrict__ out) {
    // softplus(logsumexp(mv)) = log(1 + sum(exp(mv)))
    out[0] = logf(1.0f + g_sum);
}

extern "C" void kernel_launch(void* const* d_in, const int* in_sizes, int n_in,
                              void* d_out, int out_size) {
    const float* src = (const float*)d_in[0];  // src_coords [16384, 3]
    const float* tgt = (const float*)d_in[1];  // tgt_coords [16384, 3]
    float* out = (float*)d_out;

    ml_zero_kernel<<<1, 1>>>();
    ml_nn2_kernel<<<NPTS / SRC_PER_BLOCK, THREADS>>>(src, tgt);
    ml_final_kernel<<<1, 1>>>(out);
}

// round 3
// speedup vs baseline: 1.0763x; 1.0763x over previous
#include <cuda_runtime.h>
#include <math.h>

// MatchLoss: per src point (16384x3 f32) find 2nd-nearest tgt (16384x3),
// pd = ||src - tgt[idx2] + 1e-6||, mv = (pd<1e-3)+1e-7, out = log(1+sum(exp(mv))).
//
// Inner loop uses key = 0.5*|t|^2 - s.t (monotone in distance per src): 3 FFMA/pair.
// True pd recomputed from coordinates for the winner only.
#define NPTS           16384
#define NSPLIT         8          // warps per block, each scans 1/8 of tgt tile
#define TILE           2048       // tgt points staged in SMEM per tile
#define SRC_PER_THREAD 2
#define SRC_PER_BLOCK  (32 * SRC_PER_THREAD)  // 64
#define NBLOCKS        (NPTS / SRC_PER_BLOCK) // 256
#define THREADS        256

#define RADIUS_F  1e-3f
#define EPS_F     1e-7f
#define PD_EPS_F  1e-6f
#define BIG       3.402823466e+38f

__device__ float g_partials[NBLOCKS];
__device__ int   g_count = 0;   // self-restoring: last block resets to 0

__global__ __launch_bounds__(THREADS)
void ml_nn2_kernel(const float* __restrict__ src, const float* __restrict__ tgt,
                   float* __restrict__ out) {
    __shared__ float4 tile[TILE];                    // 32 KB
    __shared__ float  sb1[NSPLIT][SRC_PER_BLOCK];
    __shared__ float  sb2[NSPLIT][SRC_PER_BLOCK];
    __shared__ int    si1[NSPLIT][SRC_PER_BLOCK];
    __shared__ int    si2[NSPLIT][SRC_PER_BLOCK];
    __shared__ float  swsum[NSPLIT];

    const int tid  = threadIdx.x;
    const int warp = tid >> 5;
    const int lane = tid & 31;

    // Each thread owns SRC_PER_THREAD src points: base + lane + 32*r.
    // Store NEGATED coords so key = fma(t, -s, ...) chains cleanly.
    const int sbase = blockIdx.x * SRC_PER_BLOCK + lane;
    float nsx[SRC_PER_THREAD], nsy[SRC_PER_THREAD], nsz[SRC_PER_THREAD];
    float b1[SRC_PER_THREAD], b2[SRC_PER_THREAD];
    int   i1[SRC_PER_THREAD], i2[SRC_PER_THREAD];
    #pragma unroll
    for (int r = 0; r < SRC_PER_THREAD; ++r) {
        const int s = sbase + 32 * r;
        nsx[r] = -src[3 * s + 0];
        nsy[r] = -src[3 * s + 1];
        nsz[r] = -src[3 * s + 2];
        b1[r] = BIG; b2[r] = BIG; i1[r] = -1; i2[r] = -1;
    }

    const int chunk = TILE / NSPLIT;   // 256 tgt points per warp per tile
    const int wbase = warp * chunk;

    for (int tb = 0; tb < NPTS; tb += TILE) {
        // Cooperative tile load (tgt is L2-resident): w slot = 0.5*|t|^2
        for (int k = tid; k < TILE; k += THREADS) {
            const int p = 3 * (tb + k);
            const float tx = tgt[p], ty = tgt[p + 1], tz = tgt[p + 2];
            const float tw = 0.5f * fmaf(tx, tx, fmaf(ty, ty, tz * tz));
            tile[k] = make_float4(tx, ty, tz, tw);
        }
        __syncthreads();

        #pragma unroll 8
        for (int k = 0; k < chunk; ++k) {
            const float4 t = tile[wbase + k];        // warp-uniform LDS.128 broadcast
            const int j = tb + wbase + k;
            #pragma unroll
            for (int r = 0; r < SRC_PER_THREAD; ++r) {
                // key = 0.5*|t|^2 - s.t : monotone in ||s-t|| for fixed s
                const float key = fmaf(t.x, nsx[r], fmaf(t.y, nsy[r], fmaf(t.z, nsz[r], t.w)));
                if (key < b2[r]) {                   // rarely taken (~2 ln N per src)
                    if (key < b1[r]) { b2[r] = b1[r]; i2[r] = i1[r]; b1[r] = key; i1[r] = j; }
                    else             { b2[r] = key;   i2[r] = j; }
                }
            }
        }
        __syncthreads();
    }

    // Publish per-split partial top-2 (key, index)
    #pragma unroll
    for (int r = 0; r < SRC_PER_THREAD; ++r) {
        sb1[warp][lane + 32 * r] = b1[r];  si1[warp][lane + 32 * r] = i1[r];
        sb2[warp][lane + 32 * r] = b2[r];  si2[warp][lane + 32 * r] = i2[r];
    }
    __syncthreads();

    // Threads 0..SRC_PER_BLOCK-1: merge 8 partials for one src point each,
    // recompute true pd for the 2nd-NN, accumulate exp(match_val).
    float contrib = 0.0f;
    if (tid < SRC_PER_BLOCK) {
        float m1 = BIG, m2 = BIG;
        int   j1 = -1,  j2 = -1;
        #pragma unroll
        for (int w = 0; w < NSPLIT; ++w) {
            float d = sb1[w][tid]; int ii = si1[w][tid];
            if (d < m2) {
                if (d < m1) { m2 = m1; j2 = j1; m1 = d; j1 = ii; }
                else        { m2 = d;  j2 = ii; }
            }
            d = sb2[w][tid]; ii = si2[w][tid];
            if (d < m2) {
                if (d < m1) { m2 = m1; j2 = j1; m1 = d; j1 = ii; }
                else        { m2 = d;  j2 = ii; }
            }
        }
        const int s = blockIdx.x * SRC_PER_BLOCK + tid;
        const float px = src[3 * s + 0], py = src[3 * s + 1], pz = src[3 * s + 2];
        const float tx = tgt[3 * j2 + 0], ty = tgt[3 * j2 + 1], tz = tgt[3 * j2 + 2];
        const float dx = px - tx + PD_EPS_F;
        const float dy = py - ty + PD_EPS_F;
        const float dz = pz - tz + PD_EPS_F;
        const float pd = sqrtf(fmaf(dx, dx, fmaf(dy, dy, dz * dz)));
        const float mv = (pd < RADIUS_F ? 1.0f : 0.0f) + EPS_F;
        contrib = expf(mv);
    }

    // Block-level reduction of the SRC_PER_BLOCK contributions
    if (tid < SRC_PER_BLOCK) {
        #pragma unroll
        for (int o = 16; o > 0; o >>= 1)
            contrib += __shfl_down_sync(0xFFFFFFFFu, contrib, o);
        if (lane == 0) swsum[warp] = contrib;
    }
    __syncthreads();

    if (tid == 0) {
        float bs = 0.0f;
        #pragma unroll
        for (int w = 0; w < SRC_PER_BLOCK / 32; ++w) bs += swsum[w];
        g_partials[blockIdx.x] = bs;
        __threadfence();
        const int done = atomicAdd(&g_count, 1);
        swsum[0] = (done == NBLOCKS - 1) ? 1.0f : 0.0f;   // am I last?
    }
    __syncthreads();

    // Last block: reduce all partials, write output, restore counter.
    if (swsum[0] != 0.0f) {
        float v = (tid < NBLOCKS) ? g_partials[tid] : 0.0f;
        #pragma unroll
        for (int o = 16; o > 0; o >>= 1)
            v += __shfl_down_sync(0xFFFFFFFFu, v, o);
        __shared__ float fin[THREADS / 32];
        if (lane == 0) fin[warp] = v;
        __syncthreads();
        if (tid == 0) {
            float s = 0.0f;
            #pragma unroll
            for (int w = 0; w < THREADS / 32; ++w) s += fin[w];
            out[0] = logf(1.0f + s);   // softplus(logsumexp(mv))
            g_count = 0;               // restore for next graph replay
        }
    }
}

extern "C" void kernel_launch(void* const* d_in, const int* in_sizes, int n_in,
                              void* d_out, int out_size) {
    const float* src = (const float*)d_in[0];  // src_coords [16384, 3]
    const float* tgt = (const float*)d_in[1];  // tgt_coords [16384, 3]
    float* out = (float*)d_out;
    ml_nn2_kernel<<<NBLOCKS, THREADS>>>(src, tgt, out);
}

// round 4
// speedup vs baseline: 1.8193x; 1.6902x over previous
#include <cuda_runtime.h>
#include <math.h>

// MatchLoss: per src point (16384x3 f32) find 2nd-nearest tgt (16384x3),
// pd = ||src - tgt[idx2]||, mv = (pd<1e-3)+1e-7, out = log(1+sum(exp(mv))).
//
// key = 0.5*|t|^2 - s.t is monotone in ||s-t|| per src: 3 FFMA/pair.
// Top-2 tracked branchlessly by VALUE only (3 FMNMX/pair); the 2nd-NN
// distance is recovered as d^2 = 2*key2 + |s|^2 (no index needed).
#define NPTS           16384
#define NSPLIT         8          // warps per block, each scans 1/8 of tgt tile
#define TILE           2048       // tgt points staged in SMEM per tile
#define SRC_PER_THREAD 2
#define SRC_PER_BLOCK  (32 * SRC_PER_THREAD)  // 64
#define NBLOCKS        (NPTS / SRC_PER_BLOCK) // 256
#define THREADS        256

#define RADIUS_F  1e-3f
#define EPS_F     1e-7f
#define BIG       3.402823466e+38f

__device__ float g_partials[NBLOCKS];
__device__ int   g_count = 0;   // self-restoring: last block resets to 0

__global__ __launch_bounds__(THREADS)
void ml_nn2_kernel(const float* __restrict__ src, const float* __restrict__ tgt,
                   float* __restrict__ out) {
    __shared__ float4 tile[TILE];                    // 32 KB
    __shared__ float  sb1[NSPLIT][SRC_PER_BLOCK];    // 2 KB
    __shared__ float  sb2[NSPLIT][SRC_PER_BLOCK];    // 2 KB
    __shared__ float  swsum[NSPLIT];

    const int tid  = threadIdx.x;
    const int warp = tid >> 5;
    const int lane = tid & 31;

    // Each thread owns SRC_PER_THREAD src points: base + lane + 32*r.
    // Store NEGATED coords so key = fma(t, -s, ...) chains cleanly.
    const int sbase = blockIdx.x * SRC_PER_BLOCK + lane;
    float nsx[SRC_PER_THREAD], nsy[SRC_PER_THREAD], nsz[SRC_PER_THREAD];
    float b1[SRC_PER_THREAD], b2[SRC_PER_THREAD];
    #pragma unroll
    for (int r = 0; r < SRC_PER_THREAD; ++r) {
        const int s = sbase + 32 * r;
        nsx[r] = -src[3 * s + 0];
        nsy[r] = -src[3 * s + 1];
        nsz[r] = -src[3 * s + 2];
        b1[r] = BIG; b2[r] = BIG;
    }

    const int chunk = TILE / NSPLIT;   // 256 tgt points per warp per tile
    const int wbase = warp * chunk;

    for (int tb = 0; tb < NPTS; tb += TILE) {
        // Cooperative tile load (tgt is L2-resident): w slot = 0.5*|t|^2
        for (int k = tid; k < TILE; k += THREADS) {
            const int p = 3 * (tb + k);
            const float tx = tgt[p], ty = tgt[p + 1], tz = tgt[p + 2];
            const float tw = 0.5f * fmaf(tx, tx, fmaf(ty, ty, tz * tz));
            tile[k] = make_float4(tx, ty, tz, tw);
        }
        __syncthreads();

        #pragma unroll 16
        for (int k = 0; k < chunk; ++k) {
            const float4 t = tile[wbase + k];        // warp-uniform LDS.128 broadcast
            #pragma unroll
            for (int r = 0; r < SRC_PER_THREAD; ++r) {
                // key = 0.5*|t|^2 - s.t : monotone in ||s-t|| for fixed s
                const float key = fmaf(t.x, nsx[r], fmaf(t.y, nsy[r], fmaf(t.z, nsz[r], t.w)));
                // exact branchless top-2 (3x FMNMX, alu pipe)
                b2[r] = fminf(b2[r], fmaxf(b1[r], key));
                b1[r] = fminf(b1[r], key);
            }
        }
        __syncthreads();
    }

    // Publish per-split partial top-2 keys
    #pragma unroll
    for (int r = 0; r < SRC_PER_THREAD; ++r) {
        sb1[warp][lane + 32 * r] = b1[r];
        sb2[warp][lane + 32 * r] = b2[r];
    }
    __syncthreads();

    // Threads 0..SRC_PER_BLOCK-1: merge 8 partials for one src point each,
    // recover d^2 of the 2nd-NN, accumulate exp(match_val).
    float contrib = 0.0f;
    if (tid < SRC_PER_BLOCK) {
        float m1 = BIG, m2 = BIG;
        #pragma unroll
        for (int w = 0; w < NSPLIT; ++w) {
            float d = sb1[w][tid];
            m2 = fminf(m2, fmaxf(m1, d));
            m1 = fminf(m1, d);
            d = sb2[w][tid];
            m2 = fminf(m2, fmaxf(m1, d));
            m1 = fminf(m1, d);
        }
        const int s = blockIdx.x * SRC_PER_BLOCK + tid;
        const float px = src[3 * s + 0], py = src[3 * s + 1], pz = src[3 * s + 2];
        const float s2 = fmaf(px, px, fmaf(py, py, pz * pz));
        const float d2 = fmaxf(fmaf(2.0f, m2, s2), 0.0f);  // ||s - t_2nd||^2
        const float pd = sqrtf(d2);
        const float mv = (pd < RADIUS_F ? 1.0f : 0.0f) + EPS_F;
        contrib = expf(mv);
    }

    // Block-level reduction of the SRC_PER_BLOCK contributions
    if (tid < SRC_PER_BLOCK) {
        #pragma unroll
        for (int o = 16; o > 0; o >>= 1)
            contrib += __shfl_down_sync(0xFFFFFFFFu, contrib, o);
        if (lane == 0) swsum[warp] = contrib;
    }
    __syncthreads();

    if (tid == 0) {
        float bs = 0.0f;
        #pragma unroll
        for (int w = 0; w < SRC_PER_BLOCK / 32; ++w) bs += swsum[w];
        g_partials[blockIdx.x] = bs;
        __threadfence();
        const int done = atomicAdd(&g_count, 1);
        swsum[0] = (done == NBLOCKS - 1) ? 1.0f : 0.0f;   // am I last?
    }
    __syncthreads();

    // Last block: reduce all partials, write output, restore counter.
    if (swsum[0] != 0.0f) {
        float v = (tid < NBLOCKS) ? g_partials[tid] : 0.0f;
        #pragma unroll
        for (int o = 16; o > 0; o >>= 1)
            v += __shfl_down_sync(0xFFFFFFFFu, v, o);
        __shared__ float fin[THREADS / 32];
        if (lane == 0) fin[warp] = v;
        __syncthreads();
        if (tid == 0) {
            float s = 0.0f;
            #pragma unroll
            for (int w = 0; w < THREADS / 32; ++w) s += fin[w];
            out[0] = logf(1.0f + s);   // softplus(logsumexp(mv))
            g_count = 0;               // restore for next graph replay
        }
    }
}

extern "C" void kernel_launch(void* const* d_in, const int* in_sizes, int n_in,
                              void* d_out, int out_size) {
    const float* src = (const float*)d_in[0];  // src_coords [16384, 3]
    const float* tgt = (const float*)d_in[1];  // tgt_coords [16384, 3]
    float* out = (float*)d_out;
    ml_nn2_kernel<<<NBLOCKS, THREADS>>>(src, tgt, out);
}